// round 2
// baseline (speedup 1.0000x reference)
#include <cuda_runtime.h>
#include <cstdint>

// ---------------------------------------------------------------------------
// Problem constants
// ---------------------------------------------------------------------------
#define BATCH 4
// Level A: coarse = xyz2 (512 pts), queries = xyz1 (2048 pts)
#define SA 512
#define NA 2048
#define GA 16
#define CA (GA*GA*GA)
// Level B: coarse = xyz1 (2048 pts), queries = xyz0 (8192 pts)
#define SB 2048
#define NB 8192
#define GB 24
#define CB (GB*GB*GB)
#define BOUND 4.5f
#define HA (2.0f*BOUND/GA)     // 0.5625
#define HB (2.0f*BOUND/GB)     // 0.375

#define D_IP1 512
#define DOUT 896
#define NOUT 8192

// ---------------------------------------------------------------------------
// Device scratch (static: no runtime allocation allowed)
// ---------------------------------------------------------------------------
__device__ int            g_cntA[BATCH*CA];
__device__ int            g_cntB[BATCH*CB];
__device__ int            g_cellA[BATCH*SA];
__device__ int            g_cellB[BATCH*SB];
__device__ float4         g_ptsA[BATCH*SA];   // (x,y,z,Sb)
__device__ float4         g_ptsB[BATCH*SB];
__device__ unsigned short g_permA[BATCH*SA];  // sorted pos -> original idx
__device__ unsigned short g_permB[BATCH*SB];
__device__ float4         g_iwA[BATCH*NA];    // {i0|i1<<16, i2, w0, w1}
__device__ float4         g_iwB[BATCH*NB];
__device__ float          g_ip1[(size_t)BATCH*D_IP1*NA];

// ---------------------------------------------------------------------------
// Helpers
// ---------------------------------------------------------------------------
__device__ __forceinline__ int cell1d(float x, float invh, int G) {
    int c = (int)floorf((x + BOUND) * invh);
    return min(max(c, 0), G - 1);
}

// Monotone map: float total order -> unsigned total order.
__device__ __forceinline__ unsigned ford(float f) {
    int ib = __float_as_int(f);
    return (unsigned)ib ^ (ib < 0 ? 0xFFFFFFFFu : 0x80000000u);
}
__device__ __forceinline__ float funord(unsigned o) {
    int ib = (o & 0x80000000u) ? (int)(o ^ 0x80000000u) : (int)~o;
    return __int_as_float(ib);
}

// ---------------------------------------------------------------------------
// Grid build
// ---------------------------------------------------------------------------
__global__ void k_zero(int* __restrict__ a, int n) {
    int i = blockIdx.x * blockDim.x + threadIdx.x;
    if (i < n) a[i] = 0;
}

__global__ void k_bin(const float* __restrict__ xyz, int S, int G, float invh,
                      int* __restrict__ cnt, int* __restrict__ cellof) {
    int i = blockIdx.x * blockDim.x + threadIdx.x;
    if (i >= BATCH * S) return;
    int b = i / S;
    const float* p = xyz + 3 * i;
    int cx = cell1d(p[0], invh, G);
    int cy = cell1d(p[1], invh, G);
    int cz = cell1d(p[2], invh, G);
    int c = (cz * G + cy) * G + cx;
    cellof[i] = c;
    atomicAdd(&cnt[b * G * G * G + c], 1);
}

// Exclusive prefix sum per batch. One block per batch.
__global__ void k_scan(int* __restrict__ cnt, int ncells) {
    __shared__ int ssum[1024];
    int b = blockIdx.x;
    int* a = cnt + b * ncells;
    int t = threadIdx.x;
    int chunk = (ncells + 1023) >> 10;
    int lo = t * chunk;
    int hi = min(lo + chunk, ncells);
    int s = 0;
    for (int i = lo; i < hi; ++i) s += a[i];
    ssum[t] = s;
    __syncthreads();
    for (int off = 1; off < 1024; off <<= 1) {
        int v = (t >= off) ? ssum[t - off] : 0;
        __syncthreads();
        ssum[t] += v;
        __syncthreads();
    }
    int run = (t == 0) ? 0 : ssum[t - 1];
    for (int i = lo; i < hi; ++i) { int c = a[i]; a[i] = run; run += c; }
}

// Scatter into cell-sorted order; store (x,y,z,Sb) and original index.
// Sb = (x*x + y*y) + z*z with pinned rounding (matches jnp.sum(b*b, -1)).
__global__ void k_scatter(const float* __restrict__ xyz, int S, int ncells,
                          int* __restrict__ cnt, const int* __restrict__ cellof,
                          float4* __restrict__ pts, unsigned short* __restrict__ perm) {
    int i = blockIdx.x * blockDim.x + threadIdx.x;
    if (i >= BATCH * S) return;
    int b = i / S;
    int s = i - b * S;
    int c = cellof[i];
    int pos = atomicAdd(&cnt[b * ncells + c], 1);
    const float* p = xyz + 3 * i;
    float x = p[0], y = p[1], z = p[2];
    float Sb = __fadd_rn(__fadd_rn(__fmul_rn(x, x), __fmul_rn(y, y)), __fmul_rn(z, z));
    pts[b * S + pos] = make_float4(x, y, z, Sb);
    perm[b * S + pos] = (unsigned short)s;
}

// ---------------------------------------------------------------------------
// 3-NN query, expanding Chebyshev shells, distances computed EXACTLY like the
// reference: d = (Sa + Sb) - 2*dot, dot = fma(a2,b2, fma(a1,b1, RN(a0*b0))).
// Top-3 kept as branch-free min/max over 64-bit keys (full d bits | sorted pos)
// -> stable tie-break, zero precision loss.
// ---------------------------------------------------------------------------
__global__ void k_query(const float* __restrict__ xyzq, int N,
                        const int* __restrict__ cnt, const float4* __restrict__ pts,
                        const unsigned short* __restrict__ perm, int S,
                        int G, float h, float invh,
                        float4* __restrict__ iw) {
    int gid = blockIdx.x * blockDim.x + threadIdx.x;
    if (gid >= BATCH * N) return;
    int b = gid / N;
    const float* q = xyzq + 3 * gid;
    float px = q[0], py = q[1], pz = q[2];
    float Sa = __fadd_rn(__fadd_rn(__fmul_rn(px, px), __fmul_rn(py, py)),
                         __fmul_rn(pz, pz));
    int cx = cell1d(px, invh, G);
    int cy = cell1d(py, invh, G);
    int cz = cell1d(pz, invh, G);
    const int*    cc = cnt + b * G * G * G;
    const float4* pp = pts + b * S;

    unsigned long long k1 = ~0ull, k2 = ~0ull, k3 = ~0ull;

    for (int r = 0; r < G; ++r) {
        int zlo = max(cz - r, 0), zhi = min(cz + r, G - 1);
        int ylo = max(cy - r, 0), yhi = min(cy + r, G - 1);
        int xlo = max(cx - r, 0), xhi = min(cx + r, G - 1);
        for (int z = zlo; z <= zhi; ++z) {
            int az = abs(z - cz);
            for (int y = ylo; y <= yhi; ++y) {
                int ay = max(az, abs(y - cy));
                for (int x = xlo; x <= xhi; ++x) {
                    if (max(ay, abs(x - cx)) != r) continue;   // shell only
                    int c = (z * G + y) * G + x;
                    int s0 = (c == 0) ? 0 : cc[c - 1];
                    int s1 = cc[c];
                    for (int i = s0; i < s1; ++i) {
                        float4 Q = pp[i];
                        float dot = __fmaf_rn(pz, Q.z,
                                    __fmaf_rn(py, Q.y, __fmul_rn(px, Q.x)));
                        float d = __fsub_rn(__fadd_rn(Sa, Q.w),
                                            __fmul_rn(2.0f, dot));
                        unsigned long long key =
                            ((unsigned long long)ford(d) << 32) | (unsigned)i;
                        unsigned long long t = min(k1, key);
                        unsigned long long m = max(k1, key); k1 = t;
                        t = min(k2, m); m = max(k2, m);      k2 = t;
                        k3 = min(k3, m);
                    }
                }
            }
        }
        if (k3 != ~0ull) {
            float rb = r * h;
            // unscanned true distance > r*h; ref-d skew <= ~3e-6 -> margin 1e-5
            unsigned thr = ford(rb * rb - 1e-5f);
            if ((unsigned)(k3 >> 32) <= thr) break;
        }
    }

    float d0 = funord((unsigned)(k1 >> 32));
    float d1 = funord((unsigned)(k2 >> 32));
    float d2 = funord((unsigned)(k3 >> 32));
    float r0 = __frcp_rn(__fadd_rn(d0, 1e-8f));
    float r1 = __frcp_rn(__fadd_rn(d1, 1e-8f));
    float r2 = __frcp_rn(__fadd_rn(d2, 1e-8f));
    float s  = __fadd_rn(__fadd_rn(r0, r1), r2);
    float w0 = __fdiv_rn(r0, s);
    float w1 = __fdiv_rn(r1, s);

    const unsigned short* pm = perm + b * S;
    int i0 = pm[(unsigned)(k1 & 0xFFFFFFFFu)];
    int i1 = pm[(unsigned)(k2 & 0xFFFFFFFFu)];
    int i2 = pm[(unsigned)(k3 & 0xFFFFFFFFu)];

    float4 o;
    o.x = __int_as_float(i0 | (i1 << 16));
    o.y = __int_as_float(i2);
    o.z = w0;
    o.w = w1;   // w2 = 1 - w0 - w1 (~1 ulp vs r2/s: negligible)
    iw[gid] = o;
}

// ---------------------------------------------------------------------------
// Stage-1 interpolation: out[b][d][n] = sum_k w_k * feat[b][d][idx_k]
// ---------------------------------------------------------------------------
template <int DT>
__global__ void k_gather(const float* __restrict__ feat, int D, int S, int N,
                         const float4* __restrict__ iw, float* __restrict__ out) {
    extern __shared__ float sm[];
    int b = blockIdx.y;
    int d0 = blockIdx.x * DT;
    const float4* fb = (const float4*)(feat + ((size_t)b * D + d0) * S);
    int tot4 = DT * S / 4;
    for (int i = threadIdx.x; i < tot4; i += blockDim.x)
        ((float4*)sm)[i] = fb[i];
    __syncthreads();

    const float4* iwb = iw + b * N;
    float* ob = out + ((size_t)b * D + d0) * N;
    for (int n = threadIdx.x; n < N; n += blockDim.x) {
        float4 v = iwb[n];
        unsigned ii = (unsigned)__float_as_int(v.x);
        int i0 = ii & 0xFFFF, i1 = ii >> 16;
        int i2 = __float_as_int(v.y);
        float w0 = v.z, w1 = v.w, w2 = 1.0f - w0 - w1;
#pragma unroll
        for (int d = 0; d < DT; ++d) {
            const float* row = sm + d * S;
            ob[(size_t)d * N + n] = fmaf(w0, row[i0], fmaf(w1, row[i1], w2 * row[i2]));
        }
    }
}

// ---------------------------------------------------------------------------
// Final stage-2 interpolation into output rows [128, 896).
// ---------------------------------------------------------------------------
template <int DT>
__global__ void k_final(const float* __restrict__ x1, const float* __restrict__ ip1,
                        const float4* __restrict__ iw, float* __restrict__ out) {
    extern __shared__ float sm[];
    const int S = 2048, N = 8192;
    int b = blockIdx.y;
    int d0 = 128 + blockIdx.x * DT;

    const int rows4 = S / 4;  // 512
    for (int i = threadIdx.x; i < DT * rows4; i += blockDim.x) {
        int j = i >> 9;
        int col = i & 511;
        int d = d0 + j;
        const float* src = (d < 384)
            ? (x1  + ((size_t)b * 256 + (d - 128)) * S)
            : (ip1 + ((size_t)b * 512 + (d - 384)) * S);
        ((float4*)sm)[i] = ((const float4*)src)[col];
    }
    __syncthreads();

    const float4* iwb = iw + b * N;
    float* ob = out + ((size_t)b * DOUT + d0) * N;
    for (int n = threadIdx.x; n < N; n += blockDim.x) {
        float4 v = iwb[n];
        unsigned ii = (unsigned)__float_as_int(v.x);
        int i0 = ii & 0xFFFF, i1 = ii >> 16;
        int i2 = __float_as_int(v.y);
        float w0 = v.z, w1 = v.w, w2 = 1.0f - w0 - w1;
#pragma unroll
        for (int d = 0; d < DT; ++d) {
            const float* row = sm + d * S;
            ob[(size_t)d * N + n] = fmaf(w0, row[i0], fmaf(w1, row[i1], w2 * row[i2]));
        }
    }
}

// Copy x0 into output rows [0, 128).
__global__ void k_copy(const float* __restrict__ x0, float* __restrict__ out) {
    const int per_b = 128 * 8192 / 4;
    int i = blockIdx.x * blockDim.x + threadIdx.x;
    if (i >= BATCH * per_b) return;
    int b = i / per_b;
    int j = i - b * per_b;
    const float4* s = (const float4*)(x0 + (size_t)b * 128 * 8192);
    float4*       d = (float4*)(out + (size_t)b * DOUT * 8192);
    d[j] = s[j];
}

// ---------------------------------------------------------------------------
// Launch
// ---------------------------------------------------------------------------
extern "C" void kernel_launch(void* const* d_in, const int* in_sizes, int n_in,
                              void* d_out, int out_size) {
    const float* xyz0 = (const float*)d_in[0];  // [4,8192,3]
    const float* xyz1 = (const float*)d_in[1];  // [4,2048,3]
    const float* xyz2 = (const float*)d_in[2];  // [4,512,3]
    const float* x0   = (const float*)d_in[3];  // [4,128,8192]
    const float* x1   = (const float*)d_in[4];  // [4,256,2048]
    const float* x2   = (const float*)d_in[5];  // [4,512,512]
    float* out = (float*)d_out;                 // [4,896,8192]

    int *cntA, *cntB, *cellA, *cellB;
    float4 *ptsA, *ptsB, *iwA, *iwB;
    unsigned short *permA, *permB;
    float* ip1;
    cudaGetSymbolAddress((void**)&cntA,  g_cntA);
    cudaGetSymbolAddress((void**)&cntB,  g_cntB);
    cudaGetSymbolAddress((void**)&cellA, g_cellA);
    cudaGetSymbolAddress((void**)&cellB, g_cellB);
    cudaGetSymbolAddress((void**)&ptsA,  g_ptsA);
    cudaGetSymbolAddress((void**)&ptsB,  g_ptsB);
    cudaGetSymbolAddress((void**)&permA, g_permA);
    cudaGetSymbolAddress((void**)&permB, g_permB);
    cudaGetSymbolAddress((void**)&iwA,   g_iwA);
    cudaGetSymbolAddress((void**)&iwB,   g_iwB);
    cudaGetSymbolAddress((void**)&ip1,   g_ip1);

    const float invHA = 1.0f / HA, invHB = 1.0f / HB;

    k_zero<<<(BATCH*CA + 255) / 256, 256>>>(cntA, BATCH*CA);
    k_zero<<<(BATCH*CB + 255) / 256, 256>>>(cntB, BATCH*CB);

    k_bin<<<(BATCH*SA + 255) / 256, 256>>>(xyz2, SA, GA, invHA, cntA, cellA);
    k_bin<<<(BATCH*SB + 255) / 256, 256>>>(xyz1, SB, GB, invHB, cntB, cellB);

    k_scan<<<BATCH, 1024>>>(cntA, CA);
    k_scan<<<BATCH, 1024>>>(cntB, CB);

    k_scatter<<<(BATCH*SA + 255) / 256, 256>>>(xyz2, SA, CA, cntA, cellA, ptsA, permA);
    k_scatter<<<(BATCH*SB + 255) / 256, 256>>>(xyz1, SB, CB, cntB, cellB, ptsB, permB);

    k_query<<<(BATCH*NA + 255) / 256, 256>>>(xyz1, NA, cntA, ptsA, permA, SA,
                                             GA, HA, invHA, iwA);
    k_query<<<(BATCH*NB + 255) / 256, 256>>>(xyz0, NB, cntB, ptsB, permB, SB,
                                             GB, HB, invHB, iwB);

    {
        dim3 grid(D_IP1 / 16, BATCH);
        size_t smem = 16 * SA * sizeof(float);  // 32 KB
        k_gather<16><<<grid, 256, smem>>>(x2, D_IP1, SA, NA, iwA, ip1);
    }

    k_copy<<<(BATCH * 128 * 8192 / 4 + 255) / 256, 256>>>(x0, out);

    {
        cudaFuncSetAttribute(k_final<16>, cudaFuncAttributeMaxDynamicSharedMemorySize,
                             16 * 2048 * (int)sizeof(float));
        dim3 grid((DOUT - 128) / 16, BATCH);
        size_t smem = 16 * 2048 * sizeof(float);  // 128 KB
        k_final<16><<<grid, 512, smem>>>(x1, ip1, iwB, out);
    }
}

// round 3
// speedup vs baseline: 2.8316x; 2.8316x over previous
#include <cuda_runtime.h>
#include <cstdint>

// ---------------------------------------------------------------------------
// Problem constants
// ---------------------------------------------------------------------------
#define BATCH 4
// Level A: coarse = xyz2 (512 pts/b), queries = xyz1 (2048 pts/b)
#define SA 512
#define NA 2048
#define GA 16
#define CA (GA*GA*GA)
// Level B: coarse = xyz1 (2048 pts/b), queries = xyz0 (8192 pts/b)
#define SB 2048
#define NB 8192
#define GB 24
#define CB (GB*GB*GB)
#define BOUND 4.5f
#define HA (2.0f*BOUND/GA)     // 0.5625
#define HB (2.0f*BOUND/GB)     // 0.375

#define D_IP1 512
#define DOUT 896
#define NOUT 8192

// ---------------------------------------------------------------------------
// Device scratch (static: no runtime allocation allowed)
// ---------------------------------------------------------------------------
__device__ int            g_cntA[BATCH*CA];
__device__ int            g_cntB[BATCH*CB];
__device__ int            g_qcntA[BATCH*CA];
__device__ int            g_qcntB[BATCH*CB];
__device__ int            g_cellA[BATCH*SA];
__device__ int            g_cellB[BATCH*SB];
__device__ int            g_qcellA[BATCH*NA];
__device__ int            g_qcellB[BATCH*NB];
__device__ float4         g_ptsA[BATCH*SA];   // (x,y,z,Sb)
__device__ float4         g_ptsB[BATCH*SB];
__device__ unsigned short g_permA[BATCH*SA];  // sorted pos -> original idx
__device__ unsigned short g_permB[BATCH*SB];
__device__ float4         g_qA[BATCH*NA];     // sorted queries (x,y,z,orig)
__device__ float4         g_qB[BATCH*NB];
__device__ float4         g_iwA[BATCH*NA];    // {i0|i1<<16, i2, w0, w1}
__device__ float4         g_iwB[BATCH*NB];
__device__ float          g_ip1[(size_t)BATCH*D_IP1*NA];

// ---------------------------------------------------------------------------
// Helpers
// ---------------------------------------------------------------------------
__device__ __forceinline__ int cell1d(float x, float invh, int G) {
    int c = (int)floorf((x + BOUND) * invh);
    return min(max(c, 0), G - 1);
}

__device__ __forceinline__ unsigned ford(float f) {
    int ib = __float_as_int(f);
    return (unsigned)ib ^ (unsigned)((ib >> 31) | 0x80000000);
}
__device__ __forceinline__ float funord(unsigned o) {
    int ib = (o & 0x80000000u) ? (int)(o ^ 0x80000000u) : (int)~o;
    return __int_as_float(ib);
}

// ---------------------------------------------------------------------------
// Grid build
// ---------------------------------------------------------------------------
__global__ void k_zero(int* __restrict__ a, int n) {
    int i = blockIdx.x * blockDim.x + threadIdx.x;
    if (i < n) a[i] = 0;
}

__global__ void k_bin(const float* __restrict__ xyz, int S, int G, float invh,
                      int* __restrict__ cnt, int* __restrict__ cellof) {
    int i = blockIdx.x * blockDim.x + threadIdx.x;
    if (i >= BATCH * S) return;
    int b = i / S;
    const float* p = xyz + 3 * i;
    int cx = cell1d(p[0], invh, G);
    int cy = cell1d(p[1], invh, G);
    int cz = cell1d(p[2], invh, G);
    int c = (cz * G + cy) * G + cx;
    cellof[i] = c;
    atomicAdd(&cnt[b * G * G * G + c], 1);
}

// Exclusive prefix sum per batch. One block per batch.
__global__ void k_scan(int* __restrict__ cnt, int ncells) {
    __shared__ int ssum[1024];
    int b = blockIdx.x;
    int* a = cnt + b * ncells;
    int t = threadIdx.x;
    int chunk = (ncells + 1023) >> 10;
    int lo = t * chunk;
    int hi = min(lo + chunk, ncells);
    int s = 0;
    for (int i = lo; i < hi; ++i) s += a[i];
    ssum[t] = s;
    __syncthreads();
    for (int off = 1; off < 1024; off <<= 1) {
        int v = (t >= off) ? ssum[t - off] : 0;
        __syncthreads();
        ssum[t] += v;
        __syncthreads();
    }
    int run = (t == 0) ? 0 : ssum[t - 1];
    for (int i = lo; i < hi; ++i) { int c = a[i]; a[i] = run; run += c; }
}

// Scatter coarse points into cell order; store (x,y,z,Sb) + original index.
// Sb = (x*x + y*y) + z*z pinned (matches jnp.sum(b*b, -1)).
__global__ void k_scatter(const float* __restrict__ xyz, int S, int ncells,
                          int* __restrict__ cnt, const int* __restrict__ cellof,
                          float4* __restrict__ pts, unsigned short* __restrict__ perm) {
    int i = blockIdx.x * blockDim.x + threadIdx.x;
    if (i >= BATCH * S) return;
    int b = i / S;
    int s = i - b * S;
    int c = cellof[i];
    int pos = atomicAdd(&cnt[b * ncells + c], 1);
    const float* p = xyz + 3 * i;
    float x = p[0], y = p[1], z = p[2];
    float Sb = __fadd_rn(__fadd_rn(__fmul_rn(x, x), __fmul_rn(y, y)), __fmul_rn(z, z));
    pts[b * S + pos] = make_float4(x, y, z, Sb);
    perm[b * S + pos] = (unsigned short)s;
}

// Scatter queries into cell order, carrying the original index in .w.
__global__ void k_scatterq(const float* __restrict__ xyz, int S, int ncells,
                           int* __restrict__ cnt, const int* __restrict__ cellof,
                           float4* __restrict__ q) {
    int i = blockIdx.x * blockDim.x + threadIdx.x;
    if (i >= BATCH * S) return;
    int b = i / S;
    int s = i - b * S;
    int c = cellof[i];
    int pos = atomicAdd(&cnt[b * ncells + c], 1);
    const float* p = xyz + 3 * i;
    q[b * S + pos] = make_float4(p[0], p[1], p[2], __int_as_float(s));
}

// ---------------------------------------------------------------------------
// 3-NN query. Distances computed EXACTLY like the reference:
//   d = (Sa + Sb) - 2*dot,  dot = fma(a2,b2, fma(a1,b1, RN(a0*b0)))
// Top-3 as 64-bit keys (full d bits | sorted pos); rare-branch insertion.
// ---------------------------------------------------------------------------
__device__ __forceinline__ void scan_range(
    const float4* __restrict__ pp, int s0, int s1,
    float px, float py, float pz, float Sa,
    unsigned long long& k1, unsigned long long& k2, unsigned long long& k3)
{
    for (int i = s0; i < s1; ++i) {
        float4 Q = __ldg(pp + i);
        float dot = __fmaf_rn(pz, Q.z, __fmaf_rn(py, Q.y, __fmul_rn(px, Q.x)));
        float d = __fsub_rn(__fadd_rn(Sa, Q.w), __fmul_rn(2.0f, dot));
        unsigned long long key = ((unsigned long long)ford(d) << 32) | (unsigned)i;
        if (key < k3) {
            unsigned long long t = min(k2, key);
            k3 = max(k2, key);
            k2 = t;
            t = min(k1, k2);
            k2 = max(k1, k2);
            k1 = t;
        }
    }
}

__device__ __forceinline__ void run_query(
    const float4* __restrict__ qs, int N,
    const int* __restrict__ cnt, const float4* __restrict__ pts,
    const unsigned short* __restrict__ perm, int S,
    int G, float h, float invh,
    float4* __restrict__ iw, int gid)
{
    float4 q4 = qs[gid];
    int b = gid / N;
    float px = q4.x, py = q4.y, pz = q4.z;
    int orig = __float_as_int(q4.w);
    float Sa = __fadd_rn(__fadd_rn(__fmul_rn(px, px), __fmul_rn(py, py)),
                         __fmul_rn(pz, pz));
    int cx = cell1d(px, invh, G);
    int cy = cell1d(py, invh, G);
    int cz = cell1d(pz, invh, G);
    const int*    cc = cnt + b * G * G * G;
    const float4* pp = pts + b * S;

    unsigned long long k1 = ~0ull, k2 = ~0ull, k3 = ~0ull;

    for (int r = 0; r < G; ++r) {
        int zlo = max(cz - r, 0), zhi = min(cz + r, G - 1);
        int ylo = max(cy - r, 0), yhi = min(cy + r, G - 1);
        int xlo = max(cx - r, 0), xhi = min(cx + r, G - 1);
        for (int z = zlo; z <= zhi; ++z) {
            bool zface = (z == cz - r) || (z == cz + r);
            for (int y = ylo; y <= yhi; ++y) {
                bool face = zface || (y == cy - r) || (y == cy + r);
                int rowbase = (z * G + y) * G;
                if (face) {
                    // whole x-row of cells is contiguous in the sorted array
                    int c0 = rowbase + xlo, c1 = rowbase + xhi;
                    int s0 = (c0 == 0) ? 0 : cc[c0 - 1];
                    int s1 = cc[c1];
                    scan_range(pp, s0, s1, px, py, pz, Sa, k1, k2, k3);
                } else {
                    int xa = cx - r, xb_ = cx + r;
                    if (xa >= 0) {
                        int c = rowbase + xa;
                        int s0 = (c == 0) ? 0 : cc[c - 1];
                        scan_range(pp, s0, cc[c], px, py, pz, Sa, k1, k2, k3);
                    }
                    if (xb_ < G) {
                        int c = rowbase + xb_;   // c >= 1 here (r >= 1)
                        scan_range(pp, cc[c - 1], cc[c], px, py, pz, Sa, k1, k2, k3);
                    }
                }
            }
        }
        if (k3 != ~0ull) {
            float rb = r * h;
            unsigned thr = ford(rb * rb - 1e-5f);  // ref-d skew margin
            if ((unsigned)(k3 >> 32) <= thr) break;
        }
    }

    float d0 = funord((unsigned)(k1 >> 32));
    float d1 = funord((unsigned)(k2 >> 32));
    float d2 = funord((unsigned)(k3 >> 32));
    float r0 = __frcp_rn(__fadd_rn(d0, 1e-8f));
    float r1 = __frcp_rn(__fadd_rn(d1, 1e-8f));
    float r2 = __frcp_rn(__fadd_rn(d2, 1e-8f));
    float s  = __fadd_rn(__fadd_rn(r0, r1), r2);
    float w0 = __fdiv_rn(r0, s);
    float w1 = __fdiv_rn(r1, s);

    const unsigned short* pm = perm + b * S;
    int i0 = pm[(unsigned)(k1 & 0xFFFFFFFFu)];
    int i1 = pm[(unsigned)(k2 & 0xFFFFFFFFu)];
    int i2 = pm[(unsigned)(k3 & 0xFFFFFFFFu)];

    float4 o;
    o.x = __int_as_float(i0 | (i1 << 16));
    o.y = __int_as_float(i2);
    o.z = w0;
    o.w = w1;   // w2 = 1 - w0 - w1
    iw[b * N + orig] = o;
}

#define QBLK 128
#define NBLKA ((BATCH*NA)/QBLK)   // 64
#define NBLKB ((BATCH*NB)/QBLK)   // 256

__global__ void k_query_all(
    const float4* __restrict__ qA, const int* __restrict__ cntA,
    const float4* __restrict__ ptsA, const unsigned short* __restrict__ permA,
    float4* __restrict__ iwA,
    const float4* __restrict__ qB, const int* __restrict__ cntB,
    const float4* __restrict__ ptsB, const unsigned short* __restrict__ permB,
    float4* __restrict__ iwB)
{
    if (blockIdx.x < NBLKA) {
        int gid = blockIdx.x * QBLK + threadIdx.x;
        run_query(qA, NA, cntA, ptsA, permA, SA, GA, HA, 1.0f / HA, iwA, gid);
    } else {
        int gid = (blockIdx.x - NBLKA) * QBLK + threadIdx.x;
        run_query(qB, NB, cntB, ptsB, permB, SB, GB, HB, 1.0f / HB, iwB, gid);
    }
}

// ---------------------------------------------------------------------------
// Stage-1 interpolation: ip1[b][d][n] = sum_k w_k * x2[b][d][idx_k]
// ---------------------------------------------------------------------------
template <int DT>
__global__ void k_gather(const float* __restrict__ feat, int D, int S, int N,
                         const float4* __restrict__ iw, float* __restrict__ out) {
    extern __shared__ float sm[];
    int b = blockIdx.y;
    int d0 = blockIdx.x * DT;
    const float4* fb = (const float4*)(feat + ((size_t)b * D + d0) * S);
    int tot4 = DT * S / 4;
    for (int i = threadIdx.x; i < tot4; i += blockDim.x)
        ((float4*)sm)[i] = fb[i];
    __syncthreads();

    const float4* iwb = iw + b * N;
    float* ob = out + ((size_t)b * D + d0) * N;
    for (int n = threadIdx.x; n < N; n += blockDim.x) {
        float4 v = iwb[n];
        unsigned ii = (unsigned)__float_as_int(v.x);
        int i0 = ii & 0xFFFF, i1 = ii >> 16;
        int i2 = __float_as_int(v.y);
        float w0 = v.z, w1 = v.w, w2 = 1.0f - w0 - w1;
#pragma unroll
        for (int d = 0; d < DT; ++d) {
            const float* row = sm + d * S;
            ob[(size_t)d * N + n] = fmaf(w0, row[i0], fmaf(w1, row[i1], w2 * row[i2]));
        }
    }
}

// ---------------------------------------------------------------------------
// Final stage-2 interpolation into output rows [128, 896).
// ---------------------------------------------------------------------------
template <int DT>
__global__ void k_final(const float* __restrict__ x1, const float* __restrict__ ip1,
                        const float4* __restrict__ iw, float* __restrict__ out) {
    extern __shared__ float sm[];
    const int S = 2048, N = 8192;
    int b = blockIdx.y;
    int d0 = 128 + blockIdx.x * DT;

    const int rows4 = S / 4;  // 512
    for (int i = threadIdx.x; i < DT * rows4; i += blockDim.x) {
        int j = i >> 9;
        int col = i & 511;
        int d = d0 + j;
        const float* src = (d < 384)
            ? (x1  + ((size_t)b * 256 + (d - 128)) * S)
            : (ip1 + ((size_t)b * 512 + (d - 384)) * S);
        ((float4*)sm)[i] = ((const float4*)src)[col];
    }
    __syncthreads();

    const float4* iwb = iw + b * N;
    float* ob = out + ((size_t)b * DOUT + d0) * N;
    for (int n = threadIdx.x; n < N; n += blockDim.x) {
        float4 v = iwb[n];
        unsigned ii = (unsigned)__float_as_int(v.x);
        int i0 = ii & 0xFFFF, i1 = ii >> 16;
        int i2 = __float_as_int(v.y);
        float w0 = v.z, w1 = v.w, w2 = 1.0f - w0 - w1;
#pragma unroll
        for (int d = 0; d < DT; ++d) {
            const float* row = sm + d * S;
            ob[(size_t)d * N + n] = fmaf(w0, row[i0], fmaf(w1, row[i1], w2 * row[i2]));
        }
    }
}

// Copy x0 into output rows [0, 128).
__global__ void k_copy(const float* __restrict__ x0, float* __restrict__ out) {
    const int per_b = 128 * 8192 / 4;
    int i = blockIdx.x * blockDim.x + threadIdx.x;
    if (i >= BATCH * per_b) return;
    int b = i / per_b;
    int j = i - b * per_b;
    const float4* s = (const float4*)(x0 + (size_t)b * 128 * 8192);
    float4*       d = (float4*)(out + (size_t)b * DOUT * 8192);
    d[j] = s[j];
}

// ---------------------------------------------------------------------------
// Launch
// ---------------------------------------------------------------------------
extern "C" void kernel_launch(void* const* d_in, const int* in_sizes, int n_in,
                              void* d_out, int out_size) {
    const float* xyz0 = (const float*)d_in[0];  // [4,8192,3]
    const float* xyz1 = (const float*)d_in[1];  // [4,2048,3]
    const float* xyz2 = (const float*)d_in[2];  // [4,512,3]
    const float* x0   = (const float*)d_in[3];  // [4,128,8192]
    const float* x1   = (const float*)d_in[4];  // [4,256,2048]
    const float* x2   = (const float*)d_in[5];  // [4,512,512]
    float* out = (float*)d_out;                 // [4,896,8192]

    int *cntA, *cntB, *qcntA, *qcntB, *cellA, *cellB, *qcellA, *qcellB;
    float4 *ptsA, *ptsB, *qA, *qB, *iwA, *iwB;
    unsigned short *permA, *permB;
    float* ip1;
    cudaGetSymbolAddress((void**)&cntA,   g_cntA);
    cudaGetSymbolAddress((void**)&cntB,   g_cntB);
    cudaGetSymbolAddress((void**)&qcntA,  g_qcntA);
    cudaGetSymbolAddress((void**)&qcntB,  g_qcntB);
    cudaGetSymbolAddress((void**)&cellA,  g_cellA);
    cudaGetSymbolAddress((void**)&cellB,  g_cellB);
    cudaGetSymbolAddress((void**)&qcellA, g_qcellA);
    cudaGetSymbolAddress((void**)&qcellB, g_qcellB);
    cudaGetSymbolAddress((void**)&ptsA,   g_ptsA);
    cudaGetSymbolAddress((void**)&ptsB,   g_ptsB);
    cudaGetSymbolAddress((void**)&qA,     g_qA);
    cudaGetSymbolAddress((void**)&qB,     g_qB);
    cudaGetSymbolAddress((void**)&permA,  g_permA);
    cudaGetSymbolAddress((void**)&permB,  g_permB);
    cudaGetSymbolAddress((void**)&iwA,    g_iwA);
    cudaGetSymbolAddress((void**)&iwB,    g_iwB);
    cudaGetSymbolAddress((void**)&ip1,    g_ip1);

    const float invHA = 1.0f / HA, invHB = 1.0f / HB;

    // 1) zero cell counts (coarse + query grids)
    k_zero<<<(BATCH*CA + 255) / 256, 256>>>(cntA,  BATCH*CA);
    k_zero<<<(BATCH*CB + 255) / 256, 256>>>(cntB,  BATCH*CB);
    k_zero<<<(BATCH*CA + 255) / 256, 256>>>(qcntA, BATCH*CA);
    k_zero<<<(BATCH*CB + 255) / 256, 256>>>(qcntB, BATCH*CB);

    // 2) bin coarse points and queries
    k_bin<<<(BATCH*SA + 255) / 256, 256>>>(xyz2, SA, GA, invHA, cntA,  cellA);
    k_bin<<<(BATCH*SB + 255) / 256, 256>>>(xyz1, SB, GB, invHB, cntB,  cellB);
    k_bin<<<(BATCH*NA + 255) / 256, 256>>>(xyz1, NA, GA, invHA, qcntA, qcellA);
    k_bin<<<(BATCH*NB + 255) / 256, 256>>>(xyz0, NB, GB, invHB, qcntB, qcellB);

    // 3) prefix sums
    k_scan<<<BATCH, 1024>>>(cntA,  CA);
    k_scan<<<BATCH, 1024>>>(cntB,  CB);
    k_scan<<<BATCH, 1024>>>(qcntA, CA);
    k_scan<<<BATCH, 1024>>>(qcntB, CB);

    // 4) scatter into cell order
    k_scatter<<<(BATCH*SA + 255) / 256, 256>>>(xyz2, SA, CA, cntA, cellA, ptsA, permA);
    k_scatter<<<(BATCH*SB + 255) / 256, 256>>>(xyz1, SB, CB, cntB, cellB, ptsB, permB);
    k_scatterq<<<(BATCH*NA + 255) / 256, 256>>>(xyz1, NA, CA, qcntA, qcellA, qA);
    k_scatterq<<<(BATCH*NB + 255) / 256, 256>>>(xyz0, NB, CB, qcntB, qcellB, qB);

    // 5) merged 3-NN queries (both levels in one launch)
    k_query_all<<<NBLKA + NBLKB, QBLK>>>(qA, cntA, ptsA, permA, iwA,
                                         qB, cntB, ptsB, permB, iwB);

    // 6) stage-1 interpolation: g_ip1[b][512][2048] from x2
    {
        dim3 grid(D_IP1 / 16, BATCH);
        size_t smem = 16 * SA * sizeof(float);  // 32 KB
        k_gather<16><<<grid, 256, smem>>>(x2, D_IP1, SA, NA, iwA, ip1);
    }

    // 7) copy x0 rows
    k_copy<<<(BATCH * 128 * 8192 / 4 + 255) / 256, 256>>>(x0, out);

    // 8) final interpolation rows [128, 896)
    {
        cudaFuncSetAttribute(k_final<8>, cudaFuncAttributeMaxDynamicSharedMemorySize,
                             8 * 2048 * (int)sizeof(float));
        dim3 grid((DOUT - 128) / 8, BATCH);
        size_t smem = 8 * 2048 * sizeof(float);  // 64 KB
        k_final<8><<<grid, 256, smem>>>(x1, ip1, iwB, out);
    }
}

// round 6
// speedup vs baseline: 3.1942x; 1.1280x over previous
#include <cuda_runtime.h>
#include <cstdint>

// ---------------------------------------------------------------------------
// Problem constants
// ---------------------------------------------------------------------------
#define BATCH 4
// Level A: coarse = xyz2 (512 pts/b), queries = xyz1 (2048 pts/b)
#define SA 512
#define NA 2048
#define GA 16
#define CA (GA*GA*GA)
// Level B: coarse = xyz1 (2048 pts/b), queries = xyz0 (8192 pts/b)
#define SB 2048
#define NB 8192
#define GB 24
#define CB (GB*GB*GB)
#define BOUND 4.5f
#define HA (2.0f*BOUND/GA)     // 0.5625
#define HB (2.0f*BOUND/GB)     // 0.375

#define D_IP1 512
#define DOUT 896
#define NOUT 8192

// ---------------------------------------------------------------------------
// Device scratch (static: no runtime allocation allowed)
// ---------------------------------------------------------------------------
__device__ int            g_cntA[BATCH*CA];
__device__ int            g_cntB[BATCH*CB];
__device__ int            g_qcntA[BATCH*CA];
__device__ int            g_qcntB[BATCH*CB];
__device__ int            g_cellA[BATCH*SA];
__device__ int            g_cellB[BATCH*SB];
__device__ int            g_qcellA[BATCH*NA];
__device__ int            g_qcellB[BATCH*NB];
__device__ float4         g_ptsA[BATCH*SA];   // (x,y,z,Sb)
__device__ float4         g_ptsB[BATCH*SB];
__device__ unsigned short g_permA[BATCH*SA];  // sorted pos -> original idx
__device__ unsigned short g_permB[BATCH*SB];
__device__ float4         g_qA[BATCH*NA];     // sorted queries (x,y,z,orig)
__device__ float4         g_qB[BATCH*NB];
__device__ float4         g_iwA[BATCH*NA];    // {i0|i1<<16, i2, w0, w1}
__device__ float4         g_iwB[BATCH*NB];
__device__ float          g_ip1[(size_t)BATCH*D_IP1*NA];

// ---------------------------------------------------------------------------
// Helpers
// ---------------------------------------------------------------------------
__device__ __forceinline__ int cell1d(float x, float invh, int G) {
    int c = (int)floorf((x + BOUND) * invh);
    return min(max(c, 0), G - 1);
}

__device__ __forceinline__ unsigned ford(float f) {
    int ib = __float_as_int(f);
    return (unsigned)ib ^ (unsigned)((ib >> 31) | 0x80000000);
}
__device__ __forceinline__ float funord(unsigned o) {
    int ib = (o & 0x80000000u) ? (int)(o ^ 0x80000000u) : (int)~o;
    return __int_as_float(ib);
}

// ---------------------------------------------------------------------------
// Fused grid build
// ---------------------------------------------------------------------------
// Segment table (compile-time):
//   seg0: coarse A  cnt=2048  xyz2  GA
//   seg1: coarse B  cnt=8192  xyz1  GB
//   seg2: query  A  cnt=8192  xyz1  GA
//   seg3: query  B  cnt=32768 xyz0  GB
#define OFF1 (BATCH*SA)                    // 2048
#define OFF2 (OFF1 + BATCH*SB)             // 10240
#define OFF3 (OFF2 + BATCH*NA)             // 18432
#define TOTPTS (OFF3 + BATCH*NB)           // 51200

__global__ void k_zero4(int* __restrict__ a0, int* __restrict__ a1,
                        int* __restrict__ a2, int* __restrict__ a3) {
    int i = blockIdx.x * blockDim.x + threadIdx.x;
    // a0,a2: BATCH*CA ints; a1,a3: BATCH*CB ints
    if (i < BATCH*CA) { a0[i] = 0; a2[i] = 0; }
    if (i < BATCH*CB) { a1[i] = 0; a3[i] = 0; }
}

__global__ void k_bin4(const float* __restrict__ xyz0,
                       const float* __restrict__ xyz1,
                       const float* __restrict__ xyz2,
                       int* __restrict__ cntA,  int* __restrict__ cellA,
                       int* __restrict__ cntB,  int* __restrict__ cellB,
                       int* __restrict__ qcntA, int* __restrict__ qcellA,
                       int* __restrict__ qcntB, int* __restrict__ qcellB) {
    int gi = blockIdx.x * blockDim.x + threadIdx.x;
    if (gi >= TOTPTS) return;
    const float* xyz; int S, G; float invh; int *cnt, *cell; int i;
    if (gi < OFF1)      { i = gi;        xyz = xyz2; S = SA; G = GA; invh = 1.0f/HA; cnt = cntA;  cell = cellA;  }
    else if (gi < OFF2) { i = gi - OFF1; xyz = xyz1; S = SB; G = GB; invh = 1.0f/HB; cnt = cntB;  cell = cellB;  }
    else if (gi < OFF3) { i = gi - OFF2; xyz = xyz1; S = NA; G = GA; invh = 1.0f/HA; cnt = qcntA; cell = qcellA; }
    else                { i = gi - OFF3; xyz = xyz0; S = NB; G = GB; invh = 1.0f/HB; cnt = qcntB; cell = qcellB; }
    int b = i / S;
    const float* p = xyz + 3 * i;
    int cx = cell1d(p[0], invh, G);
    int cy = cell1d(p[1], invh, G);
    int cz = cell1d(p[2], invh, G);
    int c = (cz * G + cy) * G + cx;
    cell[i] = c;
    atomicAdd(&cnt[b * G * G * G + c], 1);
}

// Exclusive prefix sum; 16 blocks: [which*4 + b]
__global__ void k_scan4(int* __restrict__ cntA, int* __restrict__ cntB,
                        int* __restrict__ qcntA, int* __restrict__ qcntB) {
    __shared__ int ssum[1024];
    int which = blockIdx.x >> 2;
    int b = blockIdx.x & 3;
    int* base; int ncells;
    if (which == 0)      { base = cntA;  ncells = CA; }
    else if (which == 1) { base = cntB;  ncells = CB; }
    else if (which == 2) { base = qcntA; ncells = CA; }
    else                 { base = qcntB; ncells = CB; }
    int* a = base + b * ncells;
    int t = threadIdx.x;
    int chunk = (ncells + 1023) >> 10;
    int lo = t * chunk;
    int hi = min(lo + chunk, ncells);
    int s = 0;
    for (int i = lo; i < hi; ++i) s += a[i];
    ssum[t] = s;
    __syncthreads();
    for (int off = 1; off < 1024; off <<= 1) {
        int v = (t >= off) ? ssum[t - off] : 0;
        __syncthreads();
        ssum[t] += v;
        __syncthreads();
    }
    int run = (t == 0) ? 0 : ssum[t - 1];
    for (int i = lo; i < hi; ++i) { int c = a[i]; a[i] = run; run += c; }
}

__global__ void k_scatter4(const float* __restrict__ xyz0,
                           const float* __restrict__ xyz1,
                           const float* __restrict__ xyz2,
                           int* __restrict__ cntA,  const int* __restrict__ cellA,
                           int* __restrict__ cntB,  const int* __restrict__ cellB,
                           int* __restrict__ qcntA, const int* __restrict__ qcellA,
                           int* __restrict__ qcntB, const int* __restrict__ qcellB,
                           float4* __restrict__ ptsA, unsigned short* __restrict__ permA,
                           float4* __restrict__ ptsB, unsigned short* __restrict__ permB,
                           float4* __restrict__ qA, float4* __restrict__ qB) {
    int gi = blockIdx.x * blockDim.x + threadIdx.x;
    if (gi >= TOTPTS) return;
    if (gi < OFF2) {
        // coarse sets: write (x,y,z,Sb) + perm
        const float* xyz; int S, ncells; int* cnt; const int* cell;
        float4* pts; unsigned short* perm; int i;
        if (gi < OFF1) { i = gi;        xyz = xyz2; S = SA; ncells = CA; cnt = cntA; cell = cellA; pts = ptsA; perm = permA; }
        else           { i = gi - OFF1; xyz = xyz1; S = SB; ncells = CB; cnt = cntB; cell = cellB; pts = ptsB; perm = permB; }
        int b = i / S;
        int s = i - b * S;
        int pos = atomicAdd(&cnt[b * ncells + cell[i]], 1);
        const float* p = xyz + 3 * i;
        float x = p[0], y = p[1], z = p[2];
        float Sb = __fadd_rn(__fadd_rn(__fmul_rn(x, x), __fmul_rn(y, y)), __fmul_rn(z, z));
        pts[b * S + pos] = make_float4(x, y, z, Sb);
        perm[b * S + pos] = (unsigned short)s;
    } else {
        // query sets: write (x,y,z,orig)
        const float* xyz; int S, ncells; int* cnt; const int* cell; float4* q; int i;
        if (gi < OFF3) { i = gi - OFF2; xyz = xyz1; S = NA; ncells = CA; cnt = qcntA; cell = qcellA; q = qA; }
        else           { i = gi - OFF3; xyz = xyz0; S = NB; ncells = CB; cnt = qcntB; cell = qcellB; q = qB; }
        int b = i / S;
        int s = i - b * S;
        int pos = atomicAdd(&cnt[b * ncells + cell[i]], 1);
        const float* p = xyz + 3 * i;
        q[b * S + pos] = make_float4(p[0], p[1], p[2], __int_as_float(s));
    }
}

// ---------------------------------------------------------------------------
// 3-NN query. Distances computed EXACTLY like the reference:
//   d = (Sa + Sb) - 2*dot,  dot = fma(a2,b2, fma(a1,b1, RN(a0*b0)))
// Top-3 as 64-bit keys (full d bits | sorted pos); rare-branch insertion.
// ---------------------------------------------------------------------------
__device__ __forceinline__ void scan_range(
    const float4* __restrict__ pp, int s0, int s1,
    float px, float py, float pz, float Sa,
    unsigned long long& k1, unsigned long long& k2, unsigned long long& k3)
{
    for (int i = s0; i < s1; ++i) {
        float4 Q = __ldg(pp + i);
        float dot = __fmaf_rn(pz, Q.z, __fmaf_rn(py, Q.y, __fmul_rn(px, Q.x)));
        float d = __fsub_rn(__fadd_rn(Sa, Q.w), __fmul_rn(2.0f, dot));
        unsigned long long key = ((unsigned long long)ford(d) << 32) | (unsigned)i;
        if (key < k3) {
            unsigned long long t = min(k2, key);
            k3 = max(k2, key);
            k2 = t;
            t = min(k1, k2);
            k2 = max(k1, k2);
            k1 = t;
        }
    }
}

__device__ __forceinline__ void run_query(
    const float4* __restrict__ qs, int N,
    const int* __restrict__ cnt, const float4* __restrict__ pts,
    const unsigned short* __restrict__ perm, int S,
    int G, float h, float invh,
    float4* __restrict__ iw, int gid)
{
    float4 q4 = qs[gid];
    int b = gid / N;
    float px = q4.x, py = q4.y, pz = q4.z;
    int orig = __float_as_int(q4.w);
    float Sa = __fadd_rn(__fadd_rn(__fmul_rn(px, px), __fmul_rn(py, py)),
                         __fmul_rn(pz, pz));
    int cx = cell1d(px, invh, G);
    int cy = cell1d(py, invh, G);
    int cz = cell1d(pz, invh, G);
    const int*    cc = cnt + b * G * G * G;
    const float4* pp = pts + b * S;

    unsigned long long k1 = ~0ull, k2 = ~0ull, k3 = ~0ull;

    for (int r = 0; r < G; ++r) {
        int zlo = max(cz - r, 0), zhi = min(cz + r, G - 1);
        int ylo = max(cy - r, 0), yhi = min(cy + r, G - 1);
        int xlo = max(cx - r, 0), xhi = min(cx + r, G - 1);
        for (int z = zlo; z <= zhi; ++z) {
            bool zface = (z == cz - r) || (z == cz + r);
            for (int y = ylo; y <= yhi; ++y) {
                bool face = zface || (y == cy - r) || (y == cy + r);
                int rowbase = (z * G + y) * G;
                if (face) {
                    // whole x-row of cells is contiguous in the sorted array
                    int c0 = rowbase + xlo, c1 = rowbase + xhi;
                    int s0 = (c0 == 0) ? 0 : cc[c0 - 1];
                    int s1 = cc[c1];
                    scan_range(pp, s0, s1, px, py, pz, Sa, k1, k2, k3);
                } else {
                    int xa = cx - r, xb_ = cx + r;
                    if (xa >= 0) {
                        int c = rowbase + xa;
                        int s0 = (c == 0) ? 0 : cc[c - 1];
                        scan_range(pp, s0, cc[c], px, py, pz, Sa, k1, k2, k3);
                    }
                    if (xb_ < G) {
                        int c = rowbase + xb_;   // c >= 1 here (r >= 1)
                        scan_range(pp, cc[c - 1], cc[c], px, py, pz, Sa, k1, k2, k3);
                    }
                }
            }
        }
        if (k3 != ~0ull) {
            float rb = r * h;
            unsigned thr = ford(rb * rb - 1e-5f);  // ref-d skew margin
            if ((unsigned)(k3 >> 32) <= thr) break;
        }
    }

    float d0 = funord((unsigned)(k1 >> 32));
    float d1 = funord((unsigned)(k2 >> 32));
    float d2 = funord((unsigned)(k3 >> 32));
    float r0 = __frcp_rn(__fadd_rn(d0, 1e-8f));
    float r1 = __frcp_rn(__fadd_rn(d1, 1e-8f));
    float r2 = __frcp_rn(__fadd_rn(d2, 1e-8f));
    float s  = __fadd_rn(__fadd_rn(r0, r1), r2);
    float w0 = __fdiv_rn(r0, s);
    float w1 = __fdiv_rn(r1, s);

    const unsigned short* pm = perm + b * S;
    int i0 = pm[(unsigned)(k1 & 0xFFFFFFFFu)];
    int i1 = pm[(unsigned)(k2 & 0xFFFFFFFFu)];
    int i2 = pm[(unsigned)(k3 & 0xFFFFFFFFu)];

    float4 o;
    o.x = __int_as_float(i0 | (i1 << 16));
    o.y = __int_as_float(i2);
    o.z = w0;
    o.w = w1;   // w2 = 1 - w0 - w1
    iw[b * N + orig] = o;
}

#define QBLK 64
#define NBLKA ((BATCH*NA)/QBLK)   // 128
#define NBLKB ((BATCH*NB)/QBLK)   // 512

__global__ void k_query_all(
    const float4* __restrict__ qA, const int* __restrict__ cntA,
    const float4* __restrict__ ptsA, const unsigned short* __restrict__ permA,
    float4* __restrict__ iwA,
    const float4* __restrict__ qB, const int* __restrict__ cntB,
    const float4* __restrict__ ptsB, const unsigned short* __restrict__ permB,
    float4* __restrict__ iwB)
{
    if (blockIdx.x < NBLKA) {
        int gid = blockIdx.x * QBLK + threadIdx.x;
        run_query(qA, NA, cntA, ptsA, permA, SA, GA, HA, 1.0f / HA, iwA, gid);
    } else {
        int gid = (blockIdx.x - NBLKA) * QBLK + threadIdx.x;
        run_query(qB, NB, cntB, ptsB, permB, SB, GB, HB, 1.0f / HB, iwB, gid);
    }
}

// ---------------------------------------------------------------------------
// Stage-1 interpolation: ip1[b][d][n] = sum_k w_k * x2[b][d][idx_k]
// ---------------------------------------------------------------------------
template <int DT>
__global__ void k_gather(const float* __restrict__ feat, int D, int S, int N,
                         const float4* __restrict__ iw, float* __restrict__ out) {
    extern __shared__ float sm[];
    int b = blockIdx.y;
    int d0 = blockIdx.x * DT;
    const float4* fb = (const float4*)(feat + ((size_t)b * D + d0) * S);
    int tot4 = DT * S / 4;
    for (int i = threadIdx.x; i < tot4; i += blockDim.x)
        ((float4*)sm)[i] = fb[i];
    __syncthreads();

    const float4* iwb = iw + b * N;
    float* ob = out + ((size_t)b * D + d0) * N;
    for (int n = threadIdx.x; n < N; n += blockDim.x) {
        float4 v = iwb[n];
        unsigned ii = (unsigned)__float_as_int(v.x);
        int i0 = ii & 0xFFFF, i1 = ii >> 16;
        int i2 = __float_as_int(v.y);
        float w0 = v.z, w1 = v.w, w2 = 1.0f - w0 - w1;
#pragma unroll
        for (int d = 0; d < DT; ++d) {
            const float* row = sm + d * S;
            ob[(size_t)d * N + n] = fmaf(w0, row[i0], fmaf(w1, row[i1], w2 * row[i2]));
        }
    }
}

// ---------------------------------------------------------------------------
// Final stage-2 interpolation into output rows [128, 896).
// ---------------------------------------------------------------------------
template <int DT>
__global__ void k_final(const float* __restrict__ x1, const float* __restrict__ ip1,
                        const float4* __restrict__ iw, float* __restrict__ out) {
    extern __shared__ float sm[];
    const int S = 2048, N = 8192;
    int b = blockIdx.y;
    int d0 = 128 + blockIdx.x * DT;

    const int rows4 = S / 4;  // 512
    for (int i = threadIdx.x; i < DT * rows4; i += blockDim.x) {
        int j = i >> 9;
        int col = i & 511;
        int d = d0 + j;
        const float* src = (d < 384)
            ? (x1  + ((size_t)b * 256 + (d - 128)) * S)
            : (ip1 + ((size_t)b * 512 + (d - 384)) * S);
        ((float4*)sm)[i] = ((const float4*)src)[col];
    }
    __syncthreads();

    const float4* iwb = iw + b * N;
    float* ob = out + ((size_t)b * DOUT + d0) * N;
    for (int n = threadIdx.x; n < N; n += blockDim.x) {
        float4 v = iwb[n];
        unsigned ii = (unsigned)__float_as_int(v.x);
        int i0 = ii & 0xFFFF, i1 = ii >> 16;
        int i2 = __float_as_int(v.y);
        float w0 = v.z, w1 = v.w, w2 = 1.0f - w0 - w1;
#pragma unroll
        for (int d = 0; d < DT; ++d) {
            const float* row = sm + d * S;
            ob[(size_t)d * N + n] = fmaf(w0, row[i0], fmaf(w1, row[i1], w2 * row[i2]));
        }
    }
}

// Copy x0 into output rows [0, 128).
__global__ void k_copy(const float* __restrict__ x0, float* __restrict__ out) {
    const int per_b = 128 * 8192 / 4;
    int i = blockIdx.x * blockDim.x + threadIdx.x;
    if (i >= BATCH * per_b) return;
    int b = i / per_b;
    int j = i - b * per_b;
    const float4* s = (const float4*)(x0 + (size_t)b * 128 * 8192);
    float4*       d = (float4*)(out + (size_t)b * DOUT * 8192);
    d[j] = s[j];
}

// ---------------------------------------------------------------------------
// Launch
// ---------------------------------------------------------------------------
extern "C" void kernel_launch(void* const* d_in, const int* in_sizes, int n_in,
                              void* d_out, int out_size) {
    const float* xyz0 = (const float*)d_in[0];  // [4,8192,3]
    const float* xyz1 = (const float*)d_in[1];  // [4,2048,3]
    const float* xyz2 = (const float*)d_in[2];  // [4,512,3]
    const float* x0   = (const float*)d_in[3];  // [4,128,8192]
    const float* x1   = (const float*)d_in[4];  // [4,256,2048]
    const float* x2   = (const float*)d_in[5];  // [4,512,512]
    float* out = (float*)d_out;                 // [4,896,8192]

    int *cntA, *cntB, *qcntA, *qcntB, *cellA, *cellB, *qcellA, *qcellB;
    float4 *ptsA, *ptsB, *qA, *qB, *iwA, *iwB;
    unsigned short *permA, *permB;
    float* ip1;
    cudaGetSymbolAddress((void**)&cntA,   g_cntA);
    cudaGetSymbolAddress((void**)&cntB,   g_cntB);
    cudaGetSymbolAddress((void**)&qcntA,  g_qcntA);
    cudaGetSymbolAddress((void**)&qcntB,  g_qcntB);
    cudaGetSymbolAddress((void**)&cellA,  g_cellA);
    cudaGetSymbolAddress((void**)&cellB,  g_cellB);
    cudaGetSymbolAddress((void**)&qcellA, g_qcellA);
    cudaGetSymbolAddress((void**)&qcellB, g_qcellB);
    cudaGetSymbolAddress((void**)&ptsA,   g_ptsA);
    cudaGetSymbolAddress((void**)&ptsB,   g_ptsB);
    cudaGetSymbolAddress((void**)&qA,     g_qA);
    cudaGetSymbolAddress((void**)&qB,     g_qB);
    cudaGetSymbolAddress((void**)&permA,  g_permA);
    cudaGetSymbolAddress((void**)&permB,  g_permB);
    cudaGetSymbolAddress((void**)&iwA,    g_iwA);
    cudaGetSymbolAddress((void**)&iwB,    g_iwB);
    cudaGetSymbolAddress((void**)&ip1,    g_ip1);

    // 1) zero all cell counts (one launch)
    k_zero4<<<(BATCH*CB + 255) / 256, 256>>>(cntA, cntB, qcntA, qcntB);

    // 2) bin everything (one launch)
    k_bin4<<<(TOTPTS + 255) / 256, 256>>>(xyz0, xyz1, xyz2,
                                          cntA, cellA, cntB, cellB,
                                          qcntA, qcellA, qcntB, qcellB);

    // 3) prefix sums (one launch, 16 blocks)
    k_scan4<<<16, 1024>>>(cntA, cntB, qcntA, qcntB);

    // 4) scatter into cell order (one launch)
    k_scatter4<<<(TOTPTS + 255) / 256, 256>>>(xyz0, xyz1, xyz2,
                                              cntA, cellA, cntB, cellB,
                                              qcntA, qcellA, qcntB, qcellB,
                                              ptsA, permA, ptsB, permB, qA, qB);

    // 5) copy x0 rows (independent; early so ncu -s 5 lands on the query kernel)
    k_copy<<<(BATCH * 128 * 8192 / 4 + 255) / 256, 256>>>(x0, out);

    // 6) merged 3-NN queries (both levels in one launch)
    k_query_all<<<NBLKA + NBLKB, QBLK>>>(qA, cntA, ptsA, permA, iwA,
                                         qB, cntB, ptsB, permB, iwB);

    // 7) stage-1 interpolation: g_ip1[b][512][2048] from x2
    {
        dim3 grid(D_IP1 / 16, BATCH);
        size_t smem = 16 * SA * sizeof(float);  // 32 KB
        k_gather<16><<<grid, 256, smem>>>(x2, D_IP1, SA, NA, iwA, ip1);
    }

    // 8) final interpolation rows [128, 896)
    {
        cudaFuncSetAttribute(k_final<8>, cudaFuncAttributeMaxDynamicSharedMemorySize,
                             8 * 2048 * (int)sizeof(float));
        dim3 grid((DOUT - 128) / 8, BATCH);
        size_t smem = 8 * 2048 * sizeof(float);  // 64 KB
        k_final<8><<<grid, 512, smem>>>(x1, ip1, iwB, out);
    }
}